// round 2
// baseline (speedup 1.0000x reference)
#include <cuda_runtime.h>
#include <math.h>

// Problem constants (fixed by the problem instance)
#define NTOK 8192      // B*T = 4*2048
#define CDIM 1024
#define HDIM 4096
#define EXPN 8
#define KSEL 2
#define CAPN 2048
#define NFLAT (NTOK*KSEL)

// ---------------- scratch (device globals; no allocation allowed) -------------
__device__ float g_h1[(size_t)NTOK * HDIM];          // 128 MB
__device__ float g_h2[(size_t)NTOK * HDIM];          // 128 MB
__device__ int   g_eid[NFLAT];
__device__ float g_prob[NFLAT];
__device__ int   g_pos[NFLAT];
__device__ float g_disp[(size_t)EXPN * CAPN * CDIM]; // 64 MB
__device__ float g_eh[(size_t)CAPN * HDIM];          // 32 MB (reused per expert)
__device__ float g_eo[(size_t)EXPN * CAPN * CDIM];   // 64 MB

// ---------------- generic fp32 SGEMM: C = [relu](A @ B + bias) ---------------
// A: MxK row-major, B: KxN row-major, C: MxN row-major. M,N multiples of 128,
// K multiple of 8. 128x128 block tile, 8 k-tile, 256 threads, 8x8 per thread.
template <int RELU>
__global__ __launch_bounds__(256) void sgemm_kernel(
    const float* __restrict__ A, const float* __restrict__ B,
    const float* __restrict__ bias, float* __restrict__ C,
    int M, int Nn, int Kd)
{
    __shared__ __align__(16) float As[8][128];
    __shared__ __align__(16) float Bs[8][128];

    const int tid = threadIdx.x;
    const int tx = tid & 15;          // 0..15 (col group)
    const int ty = tid >> 4;          // 0..15 (row group)
    const int bx = blockIdx.x;        // N tile
    const int by = blockIdx.y;        // M tile

    // load mapping
    const int aRow = tid >> 1;            // 0..127
    const int aCol = (tid & 1) * 4;       // 0 or 4
    const int bRow = tid >> 5;            // 0..7
    const int bCol = (tid & 31) * 4;      // 0..124

    const float* Ap = A + (size_t)(by * 128 + aRow) * Kd + aCol;
    const float* Bp = B + (size_t)bRow * Nn + (size_t)bx * 128 + bCol;

    float acc[8][8];
#pragma unroll
    for (int i = 0; i < 8; i++)
#pragma unroll
        for (int j = 0; j < 8; j++) acc[i][j] = 0.f;

    for (int k0 = 0; k0 < Kd; k0 += 8) {
        float4 a4 = *(const float4*)Ap;
        float4 b4 = *(const float4*)Bp;
        Ap += 8;
        Bp += (size_t)8 * Nn;

        As[aCol + 0][aRow] = a4.x;
        As[aCol + 1][aRow] = a4.y;
        As[aCol + 2][aRow] = a4.z;
        As[aCol + 3][aRow] = a4.w;
        *(float4*)&Bs[bRow][bCol] = b4;
        __syncthreads();

#pragma unroll
        for (int k = 0; k < 8; k++) {
            float4 a0 = *(const float4*)&As[k][ty * 4];
            float4 a1 = *(const float4*)&As[k][64 + ty * 4];
            float4 b0 = *(const float4*)&Bs[k][tx * 4];
            float4 b1 = *(const float4*)&Bs[k][64 + tx * 4];
            float ar[8] = {a0.x, a0.y, a0.z, a0.w, a1.x, a1.y, a1.z, a1.w};
            float br[8] = {b0.x, b0.y, b0.z, b0.w, b1.x, b1.y, b1.z, b1.w};
#pragma unroll
            for (int i = 0; i < 8; i++)
#pragma unroll
                for (int j = 0; j < 8; j++) acc[i][j] += ar[i] * br[j];
        }
        __syncthreads();
    }

    // epilogue: bias (+relu), float4 stores
#pragma unroll
    for (int ih = 0; ih < 2; ih++) {
#pragma unroll
        for (int i = 0; i < 4; i++) {
            int row = by * 128 + ih * 64 + ty * 4 + i;
#pragma unroll
            for (int jh = 0; jh < 2; jh++) {
                int col = bx * 128 + jh * 64 + tx * 4;
                float4 bv = *(const float4*)&bias[col];
                float4 v;
                v.x = acc[ih * 4 + i][jh * 4 + 0] + bv.x;
                v.y = acc[ih * 4 + i][jh * 4 + 1] + bv.y;
                v.z = acc[ih * 4 + i][jh * 4 + 2] + bv.z;
                v.w = acc[ih * 4 + i][jh * 4 + 3] + bv.w;
                if (RELU) {
                    v.x = fmaxf(v.x, 0.f);
                    v.y = fmaxf(v.y, 0.f);
                    v.z = fmaxf(v.z, 0.f);
                    v.w = fmaxf(v.w, 0.f);
                }
                *(float4*)&C[(size_t)row * Nn + col] = v;
            }
        }
    }
}

// -------- router head: logits (N x 8) + softmax + top-2 (jax tie rules) ------
__global__ __launch_bounds__(256) void router_topk_kernel(
    const float* __restrict__ h2, const float* __restrict__ rw3,
    const float* __restrict__ rb3, int* __restrict__ eid,
    float* __restrict__ prob)
{
    __shared__ __align__(16) float sh[HDIM];
    __shared__ float slog[EXPN];
    const int t = blockIdx.x;

    const float4* src = (const float4*)(h2 + (size_t)t * HDIM);
    float4* dst4 = (float4*)sh;
    for (int i = threadIdx.x; i < HDIM / 4; i += 256) dst4[i] = src[i];
    __syncthreads();

    const int w = threadIdx.x >> 5;
    const int lane = threadIdx.x & 31;
    if (w < EXPN) {
        float s = 0.f;
        for (int j = lane; j < HDIM; j += 32) s += sh[j] * rw3[(size_t)j * EXPN + w];
#pragma unroll
        for (int o = 16; o > 0; o >>= 1) s += __shfl_down_sync(0xffffffffu, s, o);
        if (lane == 0) slog[w] = s + rb3[w];
    }
    __syncthreads();

    if (threadIdx.x == 0) {
        float l[EXPN], p[EXPN];
        float mx = -1e30f;
#pragma unroll
        for (int e = 0; e < EXPN; e++) { l[e] = slog[e]; mx = fmaxf(mx, l[e]); }
        float se = 0.f;
#pragma unroll
        for (int e = 0; e < EXPN; e++) { p[e] = expf(l[e] - mx); se += p[e]; }
        float inv = 1.f / se;
#pragma unroll
        for (int e = 0; e < EXPN; e++) p[e] *= inv;
        // top-1: strict > keeps lowest index on ties (jax top_k semantics)
        int b1 = 0;
#pragma unroll
        for (int e = 1; e < EXPN; e++) if (p[e] > p[b1]) b1 = e;
        // top-2: lowest index among remaining with max prob
        int b2 = (b1 == 0) ? 1 : 0;
#pragma unroll
        for (int e = 0; e < EXPN; e++)
            if (e != b1 && p[e] > p[b2]) b2 = e;
        eid[t * 2 + 0] = b1; prob[t * 2 + 0] = p[b1];
        eid[t * 2 + 1] = b2; prob[t * 2 + 1] = p[b2];
    }
}

// ---- exact flattened-order per-expert ranks (single block, ordered scan) ----
__global__ __launch_bounds__(1024) void positions_kernel(
    const int* __restrict__ eid, int* __restrict__ pos)
{
    __shared__ int base[EXPN];
    __shared__ int wcnt[32][EXPN];
    const int tid = threadIdx.x;
    const int lane = tid & 31;
    const int w = tid >> 5;

    if (tid < EXPN) base[tid] = 0;
    __syncthreads();

    for (int c = 0; c < NFLAT; c += 1024) {
        if (tid < 32 * EXPN) ((int*)wcnt)[tid] = 0;
        __syncthreads();

        int e = eid[c + tid];
        unsigned m = __match_any_sync(0xffffffffu, e);
        int rank = __popc(m & ((1u << lane) - 1u));
        int leader = __ffs(m) - 1;
        if (lane == leader) wcnt[w][e] = __popc(m);
        __syncthreads();

        int off = base[e] + rank;
        for (int w2 = 0; w2 < 32; w2++)
            if (w2 < w) off += wcnt[w2][e];
        pos[c + tid] = off;
        __syncthreads();

        if (tid < EXPN) {
            int s = 0;
#pragma unroll
            for (int w2 = 0; w2 < 32; w2++) s += wcnt[w2][tid];
            base[tid] += s;
        }
        __syncthreads();
    }
}

// ---------------- zero the dispatch buffer (kernel, not memset) --------------
__global__ void zero_kernel(float4* __restrict__ p, int n4)
{
    int i = blockIdx.x * blockDim.x + threadIdx.x;
    if (i < n4) p[i] = make_float4(0.f, 0.f, 0.f, 0.f);
}

// ---------------- scatter kept tokens into expert buffers --------------------
__global__ __launch_bounds__(256) void dispatch_kernel(
    const float* __restrict__ x, const int* __restrict__ eid,
    const int* __restrict__ pos, float* __restrict__ disp)
{
    const int i = blockIdx.x;         // flat slot 0..NFLAT-1
    const int p = pos[i];
    if (p >= CAPN) return;
    const int e = eid[i];
    const int token = i >> 1;
    const float4* src = (const float4*)(x + (size_t)token * CDIM);
    float4* dst = (float4*)(disp + ((size_t)e * CAPN + p) * CDIM);
    dst[threadIdx.x] = src[threadIdx.x];   // 256 threads * float4 = 1024 floats
}

// ---------------- weighted gather-combine ------------------------------------
__global__ __launch_bounds__(256) void combine_kernel(
    const float* __restrict__ eo, const int* __restrict__ eid,
    const float* __restrict__ prob, const int* __restrict__ pos,
    float* __restrict__ out)
{
    const int t = blockIdx.x;
    const int e1 = eid[t * 2 + 0], e2 = eid[t * 2 + 1];
    const int p1 = pos[t * 2 + 0], p2 = pos[t * 2 + 1];
    const float w1 = prob[t * 2 + 0] * (p1 < CAPN ? 1.f : 0.f);
    const float w2 = prob[t * 2 + 1] * (p2 < CAPN ? 1.f : 0.f);
    const int g1 = min(p1, CAPN - 1), g2 = min(p2, CAPN - 1);

    const float4* r1 = (const float4*)(eo + ((size_t)e1 * CAPN + g1) * CDIM);
    const float4* r2 = (const float4*)(eo + ((size_t)e2 * CAPN + g2) * CDIM);
    float4 a = r1[threadIdx.x];
    float4 b = r2[threadIdx.x];
    float4 v;
    v.x = w1 * a.x + w2 * b.x;
    v.y = w1 * a.y + w2 * b.y;
    v.z = w1 * a.z + w2 * b.z;
    v.w = w1 * a.w + w2 * b.w;
    ((float4*)(out + (size_t)t * CDIM))[threadIdx.x] = v;
}

// ---------------- launch -----------------------------------------------------
extern "C" void kernel_launch(void* const* d_in, const int* in_sizes, int n_in,
                              void* d_out, int out_size)
{
    const float* x   = (const float*)d_in[0];
    const float* rw1 = (const float*)d_in[1];
    const float* rb1 = (const float*)d_in[2];
    const float* rw2 = (const float*)d_in[3];
    const float* rb2 = (const float*)d_in[4];
    const float* rw3 = (const float*)d_in[5];
    const float* rb3 = (const float*)d_in[6];
    const float* ew1 = (const float*)d_in[7];
    const float* eb1 = (const float*)d_in[8];
    const float* ew2 = (const float*)d_in[9];
    const float* eb2 = (const float*)d_in[10];
    float* out = (float*)d_out;
    (void)in_sizes; (void)n_in; (void)out_size;

    float *h1, *h2, *disp, *eh, *eo, *prob;
    int *eid, *pos;
    cudaGetSymbolAddress((void**)&h1,   g_h1);
    cudaGetSymbolAddress((void**)&h2,   g_h2);
    cudaGetSymbolAddress((void**)&disp, g_disp);
    cudaGetSymbolAddress((void**)&eh,   g_eh);
    cudaGetSymbolAddress((void**)&eo,   g_eo);
    cudaGetSymbolAddress((void**)&eid,  g_eid);
    cudaGetSymbolAddress((void**)&prob, g_prob);
    cudaGetSymbolAddress((void**)&pos,  g_pos);

    // router MLP (fp32: routing decisions must be exact-class)
    sgemm_kernel<1><<<dim3(HDIM / 128, NTOK / 128), 256>>>(x,  rw1, rb1, h1, NTOK, HDIM, CDIM);
    sgemm_kernel<1><<<dim3(HDIM / 128, NTOK / 128), 256>>>(h1, rw2, rb2, h2, NTOK, HDIM, HDIM);
    router_topk_kernel<<<NTOK, 256>>>(h2, rw3, rb3, eid, prob);

    // exact flattened-order positions + capacity
    positions_kernel<<<1, 1024>>>(eid, pos);

    // dispatch
    {
        int n4 = (int)((size_t)EXPN * CAPN * CDIM / 4);
        zero_kernel<<<(n4 + 255) / 256, 256>>>((float4*)disp, n4);
    }
    dispatch_kernel<<<NFLAT, 256>>>(x, eid, pos, disp);

    // expert FFNs (sequential, shared eh scratch)
    for (int e = 0; e < EXPN; e++) {
        sgemm_kernel<1><<<dim3(HDIM / 128, CAPN / 128), 256>>>(
            disp + (size_t)e * CAPN * CDIM, ew1 + (size_t)e * CDIM * HDIM,
            eb1 + (size_t)e * HDIM, eh, CAPN, HDIM, CDIM);
        sgemm_kernel<0><<<dim3(CDIM / 128, CAPN / 128), 256>>>(
            eh, ew2 + (size_t)e * HDIM * CDIM,
            eb2 + (size_t)e * CDIM, eo + (size_t)e * CAPN * CDIM, CAPN, CDIM, HDIM);
    }

    // combine
    combine_kernel<<<NTOK, 256>>>(eo, eid, prob, pos, out);
}

// round 4
// speedup vs baseline: 1.7290x; 1.7290x over previous
#include <cuda_runtime.h>
#include <cstdint>
#include <math.h>

// Problem constants
#define NTOK 8192
#define CDIM 1024
#define HDIM 4096
#define EXPN 8
#define KSEL 2
#define CAPN 2048
#define NFLAT (NTOK*KSEL)

// GEMM tiling: CTA 128x128, BK=16, 256 threads, warp tile 64x32 (2x4 warps)
#define BK 16
#define ROWPAD 20              // floats per smem row (16 + 4 pad, conflict-free frags)

// ---------------- scratch ----------------------------------------------------
__device__ float g_h1[(size_t)NTOK * HDIM];
__device__ float g_h2[(size_t)NTOK * HDIM];
__device__ int   g_eid[NFLAT];
__device__ float g_prob[NFLAT];
__device__ int   g_pos[NFLAT];
__device__ float g_disp[(size_t)EXPN * CAPN * CDIM];
__device__ float g_eh[(size_t)EXPN * CAPN * HDIM];
__device__ float g_eo[(size_t)EXPN * CAPN * CDIM];
__device__ float g_rw1t[(size_t)CDIM * HDIM];
__device__ float g_rw2t[(size_t)HDIM * HDIM];
__device__ float g_ew1t[(size_t)EXPN * HDIM * CDIM];
__device__ float g_ew2t[(size_t)EXPN * CDIM * HDIM];

// ---------------- helpers ------------------------------------------------
__device__ __forceinline__ uint32_t f2tf32_rna(float x) {
    uint32_t u;
    asm("cvt.rna.tf32.f32 %0, %1;" : "=r"(u) : "f"(x));
    return u;
}

#define MMA_TF32(d, a, b) \
    asm volatile( \
        "mma.sync.aligned.m16n8k8.row.col.f32.tf32.tf32.f32 " \
        "{%0,%1,%2,%3}, {%4,%5,%6,%7}, {%8,%9}, {%0,%1,%2,%3};" \
        : "+f"((d)[0]), "+f"((d)[1]), "+f"((d)[2]), "+f"((d)[3]) \
        : "r"((a)[0]), "r"((a)[1]), "r"((a)[2]), "r"((a)[3]), \
          "r"((b)[0]), "r"((b)[1]))

// ---------------- TF32 mma.sync GEMM: C = [relu](A @ Bt^T + bias) ------------
// A: [M,K] row-major. Bt: [N,K] row-major. C: [M,N] row-major.
// NPASS==3: 3xTF32 (fp32-exact class). NPASS==1: 1xTF32 (rna-rounded).
template <int NPASS, int RELU>
__global__ __launch_bounds__(256, 1)
void tf32_gemm(const float* __restrict__ A, const float* __restrict__ Bt,
               const float* __restrict__ bias, float* __restrict__ C,
               int Kd, int Nn,
               long long aB, long long bB, long long biasB, long long cB)
{
    extern __shared__ float sm[];
    // float offsets within one stage
    constexpr int AHo = 0;                       // 128 x 20
    constexpr int BHo = 128 * ROWPAD;            // 128 x 20
    constexpr int ALo = 2 * 128 * ROWPAD;
    constexpr int BLo = 3 * 128 * ROWPAD;
    constexpr int STG = (NPASS == 3 ? 4 : 2) * 128 * ROWPAD;

    const int tid = threadIdx.x;
    const int z = blockIdx.z;
    A    += (size_t)z * aB;
    Bt   += (size_t)z * bB;
    bias += (size_t)z * biasB;
    C    += (size_t)z * cB;
    const int m0 = blockIdx.y * 128;
    const int n0 = blockIdx.x * 128;

    const int warp = tid >> 5;
    const int lane = tid & 31;
    const int wm = warp >> 2;        // 0..1 -> m offset 64*wm
    const int wn = warp & 3;         // 0..3 -> n offset 32*wn
    const int g4 = lane >> 2;        // 0..7
    const int t4 = lane & 3;         // 0..3

    // gmem staging mapping: 2 float4 each for A and B per stage
    const int sr = tid >> 2;         // 0..63 base row (+64 for second f4)
    const int sc = (tid & 3) * 4;    // col within BK
    const float* aP = A + (size_t)(m0 + sr) * Kd + sc;
    const float* bP = Bt + (size_t)(n0 + sr) * Kd + sc;

    float4 pa0, pa1, pb0, pb1;
    const int nk = Kd / BK;

    auto LDG = [&](int s) {
        size_t ko = (size_t)s * BK;
        pa0 = *(const float4*)(aP + ko);
        pa1 = *(const float4*)(aP + (size_t)64 * Kd + ko);
        pb0 = *(const float4*)(bP + ko);
        pb1 = *(const float4*)(bP + (size_t)64 * Kd + ko);
    };
    auto STS = [&](int buf) {
        float* st = sm + buf * STG;
        const int o0 = sr * ROWPAD + sc;
        const int o1 = (sr + 64) * ROWPAD + sc;
        if (NPASS == 3) {
            // exact hi/lo split: hi = rna_tf32(v), lo = v - hi (exact)
            float4 v, h;
            uint4 u;
#define SPLIT_STORE(vv, base, off)                                        \
            v = vv;                                                       \
            u.x = f2tf32_rna(v.x); u.y = f2tf32_rna(v.y);                 \
            u.z = f2tf32_rna(v.z); u.w = f2tf32_rna(v.w);                 \
            h.x = __uint_as_float(u.x); h.y = __uint_as_float(u.y);       \
            h.z = __uint_as_float(u.z); h.w = __uint_as_float(u.w);       \
            *(float4*)(st + (base) + (off)) = h;                          \
            h.x = v.x - h.x; h.y = v.y - h.y;                             \
            h.z = v.z - h.z; h.w = v.w - h.w;                             \
            *(float4*)(st + (base) + 2 * 128 * ROWPAD + (off)) = h;
            SPLIT_STORE(pa0, AHo, o0)
            SPLIT_STORE(pa1, AHo, o1)
            SPLIT_STORE(pb0, BHo, o0)
            SPLIT_STORE(pb1, BHo, o1)
#undef SPLIT_STORE
        } else {
            float4 h;
#define RNA_STORE(vv, base, off)                                          \
            h.x = __uint_as_float(f2tf32_rna((vv).x));                    \
            h.y = __uint_as_float(f2tf32_rna((vv).y));                    \
            h.z = __uint_as_float(f2tf32_rna((vv).z));                    \
            h.w = __uint_as_float(f2tf32_rna((vv).w));                    \
            *(float4*)(st + (base) + (off)) = h;
            RNA_STORE(pa0, AHo, o0)
            RNA_STORE(pa1, AHo, o1)
            RNA_STORE(pb0, BHo, o0)
            RNA_STORE(pb1, BHo, o1)
#undef RNA_STORE
        }
    };

    float d[4][4][4];
#pragma unroll
    for (int i = 0; i < 4; i++)
#pragma unroll
        for (int j = 0; j < 4; j++)
#pragma unroll
            for (int q = 0; q < 4; q++) d[i][j][q] = 0.f;

    LDG(0);
    STS(0);
    if (nk > 1) LDG(1);
    __syncthreads();

    for (int s = 0; s < nk; s++) {
        const float* sb = sm + (s & 1) * STG;
#pragma unroll
        for (int kk = 0; kk < 2; kk++) {
            uint32_t ah[4][4], bh[4][2];
            const int cA = kk * 8 + t4;
#pragma unroll
            for (int i = 0; i < 4; i++) {
                int ro = (wm * 64 + i * 16 + g4) * ROWPAD + cA;
                ah[i][0] = __float_as_uint(sb[AHo + ro]);
                ah[i][1] = __float_as_uint(sb[AHo + ro + 8 * ROWPAD]);
                ah[i][2] = __float_as_uint(sb[AHo + ro + 4]);
                ah[i][3] = __float_as_uint(sb[AHo + ro + 8 * ROWPAD + 4]);
            }
#pragma unroll
            for (int j = 0; j < 4; j++) {
                int no = (wn * 32 + j * 8 + g4) * ROWPAD + cA;
                bh[j][0] = __float_as_uint(sb[BHo + no]);
                bh[j][1] = __float_as_uint(sb[BHo + no + 4]);
            }
#pragma unroll
            for (int i = 0; i < 4; i++)
#pragma unroll
                for (int j = 0; j < 4; j++) MMA_TF32(d[i][j], ah[i], bh[j]);

            if (NPASS == 3) {
                uint32_t al[4][4], bl[4][2];
#pragma unroll
                for (int i = 0; i < 4; i++) {
                    int ro = (wm * 64 + i * 16 + g4) * ROWPAD + cA;
                    al[i][0] = __float_as_uint(sb[ALo + ro]);
                    al[i][1] = __float_as_uint(sb[ALo + ro + 8 * ROWPAD]);
                    al[i][2] = __float_as_uint(sb[ALo + ro + 4]);
                    al[i][3] = __float_as_uint(sb[ALo + ro + 8 * ROWPAD + 4]);
                }
#pragma unroll
                for (int j = 0; j < 4; j++) {
                    int no = (wn * 32 + j * 8 + g4) * ROWPAD + cA;
                    bl[j][0] = __float_as_uint(sb[BLo + no]);
                    bl[j][1] = __float_as_uint(sb[BLo + no + 4]);
                }
#pragma unroll
                for (int i = 0; i < 4; i++)
#pragma unroll
                    for (int j = 0; j < 4; j++) {
                        MMA_TF32(d[i][j], ah[i], bl[j]);
                        MMA_TF32(d[i][j], al[i], bh[j]);
                    }
            }
        }
        if (s + 1 < nk) {
            STS((s + 1) & 1);
            if (s + 2 < nk) LDG(s + 2);
        }
        __syncthreads();
    }

    // epilogue: bias + relu, float2 stores
#pragma unroll
    for (int i = 0; i < 4; i++) {
        int r0 = m0 + wm * 64 + i * 16 + g4;
#pragma unroll
        for (int j = 0; j < 4; j++) {
            int col = n0 + wn * 32 + j * 8 + t4 * 2;
            float2 bv = *(const float2*)(bias + col);
            float2 v0, v1;
            v0.x = d[i][j][0] + bv.x; v0.y = d[i][j][1] + bv.y;
            v1.x = d[i][j][2] + bv.x; v1.y = d[i][j][3] + bv.y;
            if (RELU) {
                v0.x = fmaxf(v0.x, 0.f); v0.y = fmaxf(v0.y, 0.f);
                v1.x = fmaxf(v1.x, 0.f); v1.y = fmaxf(v1.y, 0.f);
            }
            *(float2*)(C + (size_t)r0 * Nn + col) = v0;
            *(float2*)(C + (size_t)(r0 + 8) * Nn + col) = v1;
        }
    }
}

// ---------------- weight transpose: W[R,Cc] -> Wt[Cc,R] ----------------------
__global__ __launch_bounds__(256) void transpose_kernel(
    const float* __restrict__ src, float* __restrict__ dst, int R, int Cc)
{
    __shared__ float tile[32][33];
    size_t off = (size_t)blockIdx.z * R * Cc;
    int c0 = blockIdx.x * 32, r0 = blockIdx.y * 32;
    int tx = threadIdx.x, ty = threadIdx.y;   // 32 x 8
#pragma unroll
    for (int i = 0; i < 4; i++)
        tile[ty + i * 8][tx] = src[off + (size_t)(r0 + ty + i * 8) * Cc + c0 + tx];
    __syncthreads();
#pragma unroll
    for (int i = 0; i < 4; i++)
        dst[off + (size_t)(c0 + ty + i * 8) * R + r0 + tx] = tile[tx][ty + i * 8];
}

// ---------------- router head ------------------------------------------------
__global__ __launch_bounds__(256) void router_topk_kernel(
    const float* __restrict__ h2, const float* __restrict__ rw3,
    const float* __restrict__ rb3, int* __restrict__ eid,
    float* __restrict__ prob)
{
    __shared__ __align__(16) float sh[HDIM];
    __shared__ float slog[EXPN];
    const int t = blockIdx.x;

    const float4* src = (const float4*)(h2 + (size_t)t * HDIM);
    float4* dst4 = (float4*)sh;
    for (int i = threadIdx.x; i < HDIM / 4; i += 256) dst4[i] = src[i];
    __syncthreads();

    const int w = threadIdx.x >> 5;
    const int lane = threadIdx.x & 31;
    if (w < EXPN) {
        float s = 0.f;
        for (int j = lane; j < HDIM; j += 32) s += sh[j] * rw3[(size_t)j * EXPN + w];
#pragma unroll
        for (int o = 16; o > 0; o >>= 1) s += __shfl_down_sync(0xffffffffu, s, o);
        if (lane == 0) slog[w] = s + rb3[w];
    }
    __syncthreads();

    if (threadIdx.x == 0) {
        float l[EXPN], p[EXPN];
        float mx = -1e30f;
#pragma unroll
        for (int e = 0; e < EXPN; e++) { l[e] = slog[e]; mx = fmaxf(mx, l[e]); }
        float se = 0.f;
#pragma unroll
        for (int e = 0; e < EXPN; e++) { p[e] = expf(l[e] - mx); se += p[e]; }
        float inv = 1.f / se;
#pragma unroll
        for (int e = 0; e < EXPN; e++) p[e] *= inv;
        int b1 = 0;
#pragma unroll
        for (int e = 1; e < EXPN; e++) if (p[e] > p[b1]) b1 = e;
        int b2 = (b1 == 0) ? 1 : 0;
#pragma unroll
        for (int e = 0; e < EXPN; e++)
            if (e != b1 && p[e] > p[b2]) b2 = e;
        eid[t * 2 + 0] = b1; prob[t * 2 + 0] = p[b1];
        eid[t * 2 + 1] = b2; prob[t * 2 + 1] = p[b2];
    }
}

// ---- exact flattened-order per-expert ranks ---------------------------------
__global__ __launch_bounds__(1024) void positions_kernel(
    const int* __restrict__ eid, int* __restrict__ pos)
{
    __shared__ int base[EXPN];
    __shared__ int wcnt[32][EXPN];
    const int tid = threadIdx.x;
    const int lane = tid & 31;
    const int w = tid >> 5;

    if (tid < EXPN) base[tid] = 0;
    __syncthreads();

    for (int c = 0; c < NFLAT; c += 1024) {
        if (tid < 32 * EXPN) ((int*)wcnt)[tid] = 0;
        __syncthreads();

        int e = eid[c + tid];
        unsigned m = __match_any_sync(0xffffffffu, e);
        int rank = __popc(m & ((1u << lane) - 1u));
        int leader = __ffs(m) - 1;
        if (lane == leader) wcnt[w][e] = __popc(m);
        __syncthreads();

        int off = base[e] + rank;
        for (int w2 = 0; w2 < 32; w2++)
            if (w2 < w) off += wcnt[w2][e];
        pos[c + tid] = off;
        __syncthreads();

        if (tid < EXPN) {
            int s = 0;
#pragma unroll
            for (int w2 = 0; w2 < 32; w2++) s += wcnt[w2][tid];
            base[tid] += s;
        }
        __syncthreads();
    }
}

__global__ void zero_kernel(float4* __restrict__ p, int n4)
{
    int i = blockIdx.x * blockDim.x + threadIdx.x;
    if (i < n4) p[i] = make_float4(0.f, 0.f, 0.f, 0.f);
}

__global__ __launch_bounds__(256) void dispatch_kernel(
    const float* __restrict__ x, const int* __restrict__ eid,
    const int* __restrict__ pos, float* __restrict__ disp)
{
    const int i = blockIdx.x;
    const int p = pos[i];
    if (p >= CAPN) return;
    const int e = eid[i];
    const int token = i >> 1;
    const float4* src = (const float4*)(x + (size_t)token * CDIM);
    float4* dst = (float4*)(disp + ((size_t)e * CAPN + p) * CDIM);
    dst[threadIdx.x] = src[threadIdx.x];
}

__global__ __launch_bounds__(256) void combine_kernel(
    const float* __restrict__ eo, const int* __restrict__ eid,
    const float* __restrict__ prob, const int* __restrict__ pos,
    float* __restrict__ out)
{
    const int t = blockIdx.x;
    const int e1 = eid[t * 2 + 0], e2 = eid[t * 2 + 1];
    const int p1 = pos[t * 2 + 0], p2 = pos[t * 2 + 1];
    const float w1 = prob[t * 2 + 0] * (p1 < CAPN ? 1.f : 0.f);
    const float w2 = prob[t * 2 + 1] * (p2 < CAPN ? 1.f : 0.f);
    const int g1 = min(p1, CAPN - 1), g2 = min(p2, CAPN - 1);

    const float4* r1 = (const float4*)(eo + ((size_t)e1 * CAPN + g1) * CDIM);
    const float4* r2 = (const float4*)(eo + ((size_t)e2 * CAPN + g2) * CDIM);
    float4 a = r1[threadIdx.x];
    float4 b = r2[threadIdx.x];
    float4 v;
    v.x = w1 * a.x + w2 * b.x;
    v.y = w1 * a.y + w2 * b.y;
    v.z = w1 * a.z + w2 * b.z;
    v.w = w1 * a.w + w2 * b.w;
    ((float4*)(out + (size_t)t * CDIM))[threadIdx.x] = v;
}

// ---------------- launch -----------------------------------------------------
extern "C" void kernel_launch(void* const* d_in, const int* in_sizes, int n_in,
                              void* d_out, int out_size)
{
    const float* x   = (const float*)d_in[0];
    const float* rw1 = (const float*)d_in[1];
    const float* rb1 = (const float*)d_in[2];
    const float* rw2 = (const float*)d_in[3];
    const float* rb2 = (const float*)d_in[4];
    const float* rw3 = (const float*)d_in[5];
    const float* rb3 = (const float*)d_in[6];
    const float* ew1 = (const float*)d_in[7];
    const float* eb1 = (const float*)d_in[8];
    const float* ew2 = (const float*)d_in[9];
    const float* eb2 = (const float*)d_in[10];
    float* out = (float*)d_out;
    (void)in_sizes; (void)n_in; (void)out_size;

    float *h1, *h2, *disp, *eh, *eo, *prob;
    float *rw1t, *rw2t, *ew1t, *ew2t;
    int *eid, *pos;
    cudaGetSymbolAddress((void**)&h1,   g_h1);
    cudaGetSymbolAddress((void**)&h2,   g_h2);
    cudaGetSymbolAddress((void**)&disp, g_disp);
    cudaGetSymbolAddress((void**)&eh,   g_eh);
    cudaGetSymbolAddress((void**)&eo,   g_eo);
    cudaGetSymbolAddress((void**)&eid,  g_eid);
    cudaGetSymbolAddress((void**)&prob, g_prob);
    cudaGetSymbolAddress((void**)&pos,  g_pos);
    cudaGetSymbolAddress((void**)&rw1t, g_rw1t);
    cudaGetSymbolAddress((void**)&rw2t, g_rw2t);
    cudaGetSymbolAddress((void**)&ew1t, g_ew1t);
    cudaGetSymbolAddress((void**)&ew2t, g_ew2t);

    const int DS3 = 4 * 128 * ROWPAD * 2 * 4;   // 2 stages * (AH,BH,AL,BL)
    const int DS1 = 2 * 128 * ROWPAD * 2 * 4;   // 2 stages * (AH,BH)
    cudaFuncSetAttribute(tf32_gemm<3,1>, cudaFuncAttributeMaxDynamicSharedMemorySize, DS3);
    cudaFuncSetAttribute(tf32_gemm<1,1>, cudaFuncAttributeMaxDynamicSharedMemorySize, DS1);
    cudaFuncSetAttribute(tf32_gemm<1,0>, cudaFuncAttributeMaxDynamicSharedMemorySize, DS1);

    // weight transposes -> [N,K]
    transpose_kernel<<<dim3(HDIM/32, CDIM/32, 1), dim3(32, 8)>>>(rw1, rw1t, CDIM, HDIM);
    transpose_kernel<<<dim3(HDIM/32, HDIM/32, 1), dim3(32, 8)>>>(rw2, rw2t, HDIM, HDIM);
    transpose_kernel<<<dim3(HDIM/32, CDIM/32, EXPN), dim3(32, 8)>>>(ew1, ew1t, CDIM, HDIM);
    transpose_kernel<<<dim3(CDIM/32, HDIM/32, EXPN), dim3(32, 8)>>>(ew2, ew2t, HDIM, CDIM);

    // router MLP (3xTF32 ~ fp32-exact class; routing decisions must not flip)
    tf32_gemm<3,1><<<dim3(HDIM/128, NTOK/128, 1), 256, DS3>>>(
        x, rw1t, rb1, h1, CDIM, HDIM, 0, 0, 0, 0);
    tf32_gemm<3,1><<<dim3(HDIM/128, NTOK/128, 1), 256, DS3>>>(
        h1, rw2t, rb2, h2, HDIM, HDIM, 0, 0, 0, 0);
    router_topk_kernel<<<NTOK, 256>>>(h2, rw3, rb3, eid, prob);
    positions_kernel<<<1, 1024>>>(eid, pos);

    // dispatch
    {
        int n4 = (int)((size_t)EXPN * CAPN * CDIM / 4);
        zero_kernel<<<(n4 + 255) / 256, 256>>>((float4*)disp, n4);
    }
    dispatch_kernel<<<NFLAT, 256>>>(x, eid, pos, disp);

    // expert FFNs (1xTF32-rna: values only, positions fixed), batched over z
    tf32_gemm<1,1><<<dim3(HDIM/128, CAPN/128, EXPN), 256, DS1>>>(
        disp, ew1t, eb1, eh, CDIM, HDIM,
        (long long)CAPN * CDIM, (long long)HDIM * CDIM, HDIM, (long long)CAPN * HDIM);
    tf32_gemm<1,0><<<dim3(CDIM/128, CAPN/128, EXPN), 256, DS1>>>(
        eh, ew2t, eb2, eo, HDIM, CDIM,
        (long long)CAPN * HDIM, (long long)CDIM * HDIM, CDIM, (long long)CAPN * CDIM);

    // combine
    combine_kernel<<<NTOK, 256>>>(eo, eid, prob, pos, out);
}

// round 5
// speedup vs baseline: 1.9017x; 1.0999x over previous
#include <cuda_runtime.h>
#include <cstdint>
#include <math.h>

// Problem constants
#define NTOK 8192
#define CDIM 1024
#define HDIM 4096
#define EXPN 8
#define KSEL 2
#define CAPN 2048
#define NFLAT (NTOK*KSEL)

// GEMM tiling: CTA 128x128, BK=32, 256 threads, warp tile 64x32 (2x4 warps)
#define BK2 32
#define RP 36                 // floats per smem row (32 + 4 pad; 144B, 16B-aligned)
#define NST 3                 // cp.async stages
#define TILEF (128*RP)        // floats per tile

// ---------------- scratch ----------------------------------------------------
__device__ float g_xh[(size_t)NTOK * CDIM];
__device__ float g_xl[(size_t)NTOK * CDIM];
__device__ float g_h1h[(size_t)NTOK * HDIM];
__device__ float g_h1l[(size_t)NTOK * HDIM];
__device__ float g_h2[(size_t)NTOK * HDIM];
__device__ int   g_eid[NFLAT];
__device__ float g_prob[NFLAT];
__device__ int   g_pos[NFLAT];
__device__ float g_disp[(size_t)EXPN * CAPN * CDIM];
__device__ float g_eh[(size_t)EXPN * CAPN * HDIM];
__device__ float g_eo[(size_t)EXPN * CAPN * CDIM];
__device__ float g_rw1th[(size_t)HDIM * CDIM];
__device__ float g_rw1tl[(size_t)HDIM * CDIM];
__device__ float g_rw2th[(size_t)HDIM * HDIM];
__device__ float g_rw2tl[(size_t)HDIM * HDIM];
__device__ float g_ew1t[(size_t)EXPN * HDIM * CDIM];
__device__ float g_ew2t[(size_t)EXPN * CDIM * HDIM];

// ---------------- helpers ------------------------------------------------
__device__ __forceinline__ uint32_t f2tf32_rna(float x) {
    uint32_t u;
    asm("cvt.rna.tf32.f32 %0, %1;" : "=r"(u) : "f"(x));
    return u;
}
__device__ __forceinline__ uint32_t smem_u32(const void* p) {
    uint32_t a;
    asm("{ .reg .u64 t; cvta.to.shared.u64 t, %1; cvt.u32.u64 %0, t; }" : "=r"(a) : "l"(p));
    return a;
}
__device__ __forceinline__ void cp16(uint32_t s, const float* g) {
    asm volatile("cp.async.cg.shared.global [%0], [%1], 16;" :: "r"(s), "l"(g));
}
__device__ __forceinline__ void cp_commit() {
    asm volatile("cp.async.commit_group;" ::: "memory");
}
template <int N> __device__ __forceinline__ void cp_wait() {
    asm volatile("cp.async.wait_group %0;" :: "n"(N) : "memory");
}

#define MMA_TF32(d, a, b) \
    asm volatile( \
        "mma.sync.aligned.m16n8k8.row.col.f32.tf32.tf32.f32 " \
        "{%0,%1,%2,%3}, {%4,%5,%6,%7}, {%8,%9}, {%0,%1,%2,%3};" \
        : "+f"((d)[0]), "+f"((d)[1]), "+f"((d)[2]), "+f"((d)[3]) \
        : "r"((a)[0]), "r"((a)[1]), "r"((a)[2]), "r"((a)[3]), \
          "r"((b)[0]), "r"((b)[1]))

// ---------------- TF32 mma.sync GEMM (pre-converted operands) ----------------
// Ah/Al: [M,K] row-major (Al used iff PASS3). Bh/Bl: [N,K] row-major.
// C = op(A@B^T + bias). WMODE: 0 plain fp32, 1 write (hi,lo) split, 2 write rna.
template <int PASS3, int RELU, int WMODE>
__global__ __launch_bounds__(256, 1)
void mma_gemm(const float* __restrict__ Ah, const float* __restrict__ Al,
              const float* __restrict__ Bh, const float* __restrict__ Bl,
              const float* __restrict__ bias, float* __restrict__ C,
              float* __restrict__ Cl,
              int Kd, int Nn,
              long long aB, long long bB, long long biasB, long long cB)
{
    extern __shared__ float sm[];
    constexpr int AHo = 0;
    constexpr int BHo = TILEF;
    constexpr int ALo = 2 * TILEF;
    constexpr int BLo = 3 * TILEF;
    constexpr int STG = (PASS3 ? 4 : 2) * TILEF;

    const int tid = threadIdx.x;
    const int z = blockIdx.z;
    Ah += (size_t)z * aB;
    Bh += (size_t)z * bB;
    if (PASS3) { Al += (size_t)z * aB; Bl += (size_t)z * bB; }
    bias += (size_t)z * biasB;
    C    += (size_t)z * cB;
    if (WMODE == 1) Cl += (size_t)z * cB;
    const int m0 = blockIdx.y * 128;
    const int n0 = blockIdx.x * 128;

    const int warp = tid >> 5;
    const int lane = tid & 31;
    const int wm = warp >> 2;
    const int wn = warp & 3;
    const int g4 = lane >> 2;
    const int t4 = lane & 3;

    const uint32_t smb = smem_u32(sm);
    const int nk = Kd / BK2;

    // loader mapping: 4 chunks of 16B per tile per thread
    int lrow[4], lc4[4];
#pragma unroll
    for (int t = 0; t < 4; t++) {
        int id = tid + 256 * t;
        lrow[t] = id >> 3;
        lc4[t] = (id & 7) * 4;
    }

    auto ISSUE = [&](int s) {
        const int buf = s % NST;
        const uint32_t sb = smb + (uint32_t)buf * STG * 4;
        const size_t ko = (size_t)s * BK2;
#pragma unroll
        for (int t = 0; t < 4; t++) {
            const size_t go = (size_t)lrow[t] * Kd + ko + lc4[t];
            const uint32_t so = (uint32_t)(lrow[t] * RP + lc4[t]) * 4;
            cp16(sb + AHo * 4 + so, Ah + (size_t)m0 * Kd + go);
            cp16(sb + BHo * 4 + so, Bh + (size_t)n0 * Kd + go);
            if (PASS3) {
                cp16(sb + ALo * 4 + so, Al + (size_t)m0 * Kd + go);
                cp16(sb + BLo * 4 + so, Bl + (size_t)n0 * Kd + go);
            }
        }
    };

    float d[4][4][4];
#pragma unroll
    for (int i = 0; i < 4; i++)
#pragma unroll
        for (int j = 0; j < 4; j++)
#pragma unroll
            for (int q = 0; q < 4; q++) d[i][j][q] = 0.f;

    // prologue: 2 stages in flight
    ISSUE(0); cp_commit();
    if (nk > 1) ISSUE(1);
    cp_commit();

    for (int s = 0; s < nk; s++) {
        cp_wait<NST - 2>();
        __syncthreads();
        if (s + NST - 1 < nk) ISSUE(s + NST - 1);
        cp_commit();

        const float* sb = sm + (s % NST) * STG;
#pragma unroll
        for (int kk = 0; kk < 4; kk++) {
            const int cA = kk * 8 + t4;
            uint32_t ah[4][4], bh[4][2];
#pragma unroll
            for (int i = 0; i < 4; i++) {
                int ro = (wm * 64 + i * 16 + g4) * RP + cA;
                ah[i][0] = __float_as_uint(sb[AHo + ro]);
                ah[i][1] = __float_as_uint(sb[AHo + ro + 8 * RP]);
                ah[i][2] = __float_as_uint(sb[AHo + ro + 4]);
                ah[i][3] = __float_as_uint(sb[AHo + ro + 8 * RP + 4]);
            }
#pragma unroll
            for (int j = 0; j < 4; j++) {
                int no = (wn * 32 + j * 8 + g4) * RP + cA;
                bh[j][0] = __float_as_uint(sb[BHo + no]);
                bh[j][1] = __float_as_uint(sb[BHo + no + 4]);
            }
#pragma unroll
            for (int i = 0; i < 4; i++)
#pragma unroll
                for (int j = 0; j < 4; j++) MMA_TF32(d[i][j], ah[i], bh[j]);

            if (PASS3) {
                uint32_t al[4][4], bl[4][2];
#pragma unroll
                for (int i = 0; i < 4; i++) {
                    int ro = (wm * 64 + i * 16 + g4) * RP + cA;
                    al[i][0] = __float_as_uint(sb[ALo + ro]);
                    al[i][1] = __float_as_uint(sb[ALo + ro + 8 * RP]);
                    al[i][2] = __float_as_uint(sb[ALo + ro + 4]);
                    al[i][3] = __float_as_uint(sb[ALo + ro + 8 * RP + 4]);
                }
#pragma unroll
                for (int j = 0; j < 4; j++) {
                    int no = (wn * 32 + j * 8 + g4) * RP + cA;
                    bl[j][0] = __float_as_uint(sb[BLo + no]);
                    bl[j][1] = __float_as_uint(sb[BLo + no + 4]);
                }
#pragma unroll
                for (int i = 0; i < 4; i++)
#pragma unroll
                    for (int j = 0; j < 4; j++) {
                        MMA_TF32(d[i][j], ah[i], bl[j]);
                        MMA_TF32(d[i][j], al[i], bh[j]);
                    }
            }
        }
    }

    // epilogue
#pragma unroll
    for (int i = 0; i < 4; i++) {
        int r0 = m0 + wm * 64 + i * 16 + g4;
#pragma unroll
        for (int j = 0; j < 4; j++) {
            int col = n0 + wn * 32 + j * 8 + t4 * 2;
            float2 bv = *(const float2*)(bias + col);
            float vv[4];
            vv[0] = d[i][j][0] + bv.x; vv[1] = d[i][j][1] + bv.y;
            vv[2] = d[i][j][2] + bv.x; vv[3] = d[i][j][3] + bv.y;
            if (RELU) {
#pragma unroll
                for (int q = 0; q < 4; q++) vv[q] = fmaxf(vv[q], 0.f);
            }
            size_t o0 = (size_t)r0 * Nn + col;
            size_t o1 = (size_t)(r0 + 8) * Nn + col;
            if (WMODE == 0) {
                *(float2*)(C + o0) = make_float2(vv[0], vv[1]);
                *(float2*)(C + o1) = make_float2(vv[2], vv[3]);
            } else if (WMODE == 2) {
                float2 h0, h1;
                h0.x = __uint_as_float(f2tf32_rna(vv[0]));
                h0.y = __uint_as_float(f2tf32_rna(vv[1]));
                h1.x = __uint_as_float(f2tf32_rna(vv[2]));
                h1.y = __uint_as_float(f2tf32_rna(vv[3]));
                *(float2*)(C + o0) = h0;
                *(float2*)(C + o1) = h1;
            } else {
                float2 h0, h1, l0, l1;
                h0.x = __uint_as_float(f2tf32_rna(vv[0]));
                h0.y = __uint_as_float(f2tf32_rna(vv[1]));
                h1.x = __uint_as_float(f2tf32_rna(vv[2]));
                h1.y = __uint_as_float(f2tf32_rna(vv[3]));
                l0.x = vv[0] - h0.x; l0.y = vv[1] - h0.y;
                l1.x = vv[2] - h1.x; l1.y = vv[3] - h1.y;
                *(float2*)(C + o0)  = h0;
                *(float2*)(C + o1)  = h1;
                *(float2*)(Cl + o0) = l0;
                *(float2*)(Cl + o1) = l1;
            }
        }
    }
}

// ---------------- elementwise split: x -> (rna(x), x - rna(x)) ---------------
__global__ __launch_bounds__(256) void split_kernel(
    const float* __restrict__ src, float* __restrict__ dh, float* __restrict__ dl,
    int n4)
{
    int i = blockIdx.x * blockDim.x + threadIdx.x;
    if (i >= n4) return;
    float4 v = ((const float4*)src)[i];
    float4 h, l;
    h.x = __uint_as_float(f2tf32_rna(v.x)); l.x = v.x - h.x;
    h.y = __uint_as_float(f2tf32_rna(v.y)); l.y = v.y - h.y;
    h.z = __uint_as_float(f2tf32_rna(v.z)); l.z = v.z - h.z;
    h.w = __uint_as_float(f2tf32_rna(v.w)); l.w = v.w - h.w;
    ((float4*)dh)[i] = h;
    ((float4*)dl)[i] = l;
}

// ------------- weight transpose W[R,Cc]->Wt[Cc,R], MODE: 0 split, 1 rna ------
template <int MODE>
__global__ __launch_bounds__(256) void transpose_kernel(
    const float* __restrict__ src, float* __restrict__ dh, float* __restrict__ dl,
    int R, int Cc)
{
    __shared__ float tile[32][33];
    size_t off = (size_t)blockIdx.z * R * Cc;
    int c0 = blockIdx.x * 32, r0 = blockIdx.y * 32;
    int tx = threadIdx.x, ty = threadIdx.y;   // 32 x 8
#pragma unroll
    for (int i = 0; i < 4; i++)
        tile[ty + i * 8][tx] = src[off + (size_t)(r0 + ty + i * 8) * Cc + c0 + tx];
    __syncthreads();
#pragma unroll
    for (int i = 0; i < 4; i++) {
        float v = tile[tx][ty + i * 8];
        float h = __uint_as_float(f2tf32_rna(v));
        size_t o = off + (size_t)(c0 + ty + i * 8) * R + r0 + tx;
        dh[o] = h;
        if (MODE == 0) dl[o] = v - h;
    }
}

// ---------------- router head ------------------------------------------------
__global__ __launch_bounds__(256) void router_topk_kernel(
    const float* __restrict__ h2, const float* __restrict__ rw3,
    const float* __restrict__ rb3, int* __restrict__ eid,
    float* __restrict__ prob)
{
    __shared__ __align__(16) float sh[HDIM];
    __shared__ float slog[EXPN];
    const int t = blockIdx.x;

    const float4* src = (const float4*)(h2 + (size_t)t * HDIM);
    float4* dst4 = (float4*)sh;
    for (int i = threadIdx.x; i < HDIM / 4; i += 256) dst4[i] = src[i];
    __syncthreads();

    const int w = threadIdx.x >> 5;
    const int lane = threadIdx.x & 31;
    if (w < EXPN) {
        float s = 0.f;
        for (int j = lane; j < HDIM; j += 32) s += sh[j] * rw3[(size_t)j * EXPN + w];
#pragma unroll
        for (int o = 16; o > 0; o >>= 1) s += __shfl_down_sync(0xffffffffu, s, o);
        if (lane == 0) slog[w] = s + rb3[w];
    }
    __syncthreads();

    if (threadIdx.x == 0) {
        float l[EXPN], p[EXPN];
        float mx = -1e30f;
#pragma unroll
        for (int e = 0; e < EXPN; e++) { l[e] = slog[e]; mx = fmaxf(mx, l[e]); }
        float se = 0.f;
#pragma unroll
        for (int e = 0; e < EXPN; e++) { p[e] = expf(l[e] - mx); se += p[e]; }
        float inv = 1.f / se;
#pragma unroll
        for (int e = 0; e < EXPN; e++) p[e] *= inv;
        int b1 = 0;
#pragma unroll
        for (int e = 1; e < EXPN; e++) if (p[e] > p[b1]) b1 = e;
        int b2 = (b1 == 0) ? 1 : 0;
#pragma unroll
        for (int e = 0; e < EXPN; e++)
            if (e != b1 && p[e] > p[b2]) b2 = e;
        eid[t * 2 + 0] = b1; prob[t * 2 + 0] = p[b1];
        eid[t * 2 + 1] = b2; prob[t * 2 + 1] = p[b2];
    }
}

// ---- exact flattened-order per-expert ranks ---------------------------------
__global__ __launch_bounds__(1024) void positions_kernel(
    const int* __restrict__ eid, int* __restrict__ pos)
{
    __shared__ int base[EXPN];
    __shared__ int wcnt[32][EXPN];
    const int tid = threadIdx.x;
    const int lane = tid & 31;
    const int w = tid >> 5;

    if (tid < EXPN) base[tid] = 0;
    __syncthreads();

    for (int c = 0; c < NFLAT; c += 1024) {
        if (tid < 32 * EXPN) ((int*)wcnt)[tid] = 0;
        __syncthreads();

        int e = eid[c + tid];
        unsigned m = __match_any_sync(0xffffffffu, e);
        int rank = __popc(m & ((1u << lane) - 1u));
        int leader = __ffs(m) - 1;
        if (lane == leader) wcnt[w][e] = __popc(m);
        __syncthreads();

        int off = base[e] + rank;
        for (int w2 = 0; w2 < 32; w2++)
            if (w2 < w) off += wcnt[w2][e];
        pos[c + tid] = off;
        __syncthreads();

        if (tid < EXPN) {
            int s = 0;
#pragma unroll
            for (int w2 = 0; w2 < 32; w2++) s += wcnt[w2][tid];
            base[tid] += s;
        }
        __syncthreads();
    }
}

__global__ void zero_kernel(float4* __restrict__ p, int n4)
{
    int i = blockIdx.x * blockDim.x + threadIdx.x;
    if (i < n4) p[i] = make_float4(0.f, 0.f, 0.f, 0.f);
}

// dispatch: scatter rna(x) rows into expert buffers
__global__ __launch_bounds__(256) void dispatch_kernel(
    const float* __restrict__ x, const int* __restrict__ eid,
    const int* __restrict__ pos, float* __restrict__ disp)
{
    const int i = blockIdx.x;
    const int p = pos[i];
    if (p >= CAPN) return;
    const int e = eid[i];
    const int token = i >> 1;
    const float4* src = (const float4*)(x + (size_t)token * CDIM);
    float4* dst = (float4*)(disp + ((size_t)e * CAPN + p) * CDIM);
    float4 v = src[threadIdx.x];
    v.x = __uint_as_float(f2tf32_rna(v.x));
    v.y = __uint_as_float(f2tf32_rna(v.y));
    v.z = __uint_as_float(f2tf32_rna(v.z));
    v.w = __uint_as_float(f2tf32_rna(v.w));
    dst[threadIdx.x] = v;
}

__global__ __launch_bounds__(256) void combine_kernel(
    const float* __restrict__ eo, const int* __restrict__ eid,
    const float* __restrict__ prob, const int* __restrict__ pos,
    float* __restrict__ out)
{
    const int t = blockIdx.x;
    const int e1 = eid[t * 2 + 0], e2 = eid[t * 2 + 1];
    const int p1 = pos[t * 2 + 0], p2 = pos[t * 2 + 1];
    const float w1 = prob[t * 2 + 0] * (p1 < CAPN ? 1.f : 0.f);
    const float w2 = prob[t * 2 + 1] * (p2 < CAPN ? 1.f : 0.f);
    const int g1 = min(p1, CAPN - 1), g2 = min(p2, CAPN - 1);

    const float4* r1 = (const float4*)(eo + ((size_t)e1 * CAPN + g1) * CDIM);
    const float4* r2 = (const float4*)(eo + ((size_t)e2 * CAPN + g2) * CDIM);
    float4 a = r1[threadIdx.x];
    float4 b = r2[threadIdx.x];
    float4 v;
    v.x = w1 * a.x + w2 * b.x;
    v.y = w1 * a.y + w2 * b.y;
    v.z = w1 * a.z + w2 * b.z;
    v.w = w1 * a.w + w2 * b.w;
    ((float4*)(out + (size_t)t * CDIM))[threadIdx.x] = v;
}

// ---------------- launch -----------------------------------------------------
extern "C" void kernel_launch(void* const* d_in, const int* in_sizes, int n_in,
                              void* d_out, int out_size)
{
    const float* x   = (const float*)d_in[0];
    const float* rw1 = (const float*)d_in[1];
    const float* rb1 = (const float*)d_in[2];
    const float* rw2 = (const float*)d_in[3];
    const float* rb2 = (const float*)d_in[4];
    const float* rw3 = (const float*)d_in[5];
    const float* rb3 = (const float*)d_in[6];
    const float* ew1 = (const float*)d_in[7];
    const float* eb1 = (const float*)d_in[8];
    const float* ew2 = (const float*)d_in[9];
    const float* eb2 = (const float*)d_in[10];
    float* out = (float*)d_out;
    (void)in_sizes; (void)n_in; (void)out_size;

    float *xh, *xl, *h1h, *h1l, *h2, *disp, *eh, *eo, *prob;
    float *rw1th, *rw1tl, *rw2th, *rw2tl, *ew1t, *ew2t;
    int *eid, *pos;
    cudaGetSymbolAddress((void**)&xh,    g_xh);
    cudaGetSymbolAddress((void**)&xl,    g_xl);
    cudaGetSymbolAddress((void**)&h1h,   g_h1h);
    cudaGetSymbolAddress((void**)&h1l,   g_h1l);
    cudaGetSymbolAddress((void**)&h2,    g_h2);
    cudaGetSymbolAddress((void**)&disp,  g_disp);
    cudaGetSymbolAddress((void**)&eh,    g_eh);
    cudaGetSymbolAddress((void**)&eo,    g_eo);
    cudaGetSymbolAddress((void**)&eid,   g_eid);
    cudaGetSymbolAddress((void**)&prob,  g_prob);
    cudaGetSymbolAddress((void**)&pos,   g_pos);
    cudaGetSymbolAddress((void**)&rw1th, g_rw1th);
    cudaGetSymbolAddress((void**)&rw1tl, g_rw1tl);
    cudaGetSymbolAddress((void**)&rw2th, g_rw2th);
    cudaGetSymbolAddress((void**)&rw2tl, g_rw2tl);
    cudaGetSymbolAddress((void**)&ew1t,  g_ew1t);
    cudaGetSymbolAddress((void**)&ew2t,  g_ew2t);

    const int DS3 = 4 * TILEF * NST * 4;   // 3-pass: AH,BH,AL,BL per stage
    const int DS1 = 2 * TILEF * NST * 4;   // 1-pass: AH,BH per stage
    cudaFuncSetAttribute(mma_gemm<1,1,1>, cudaFuncAttributeMaxDynamicSharedMemorySize, DS3);
    cudaFuncSetAttribute(mma_gemm<1,1,0>, cudaFuncAttributeMaxDynamicSharedMemorySize, DS3);
    cudaFuncSetAttribute(mma_gemm<0,1,2>, cudaFuncAttributeMaxDynamicSharedMemorySize, DS1);
    cudaFuncSetAttribute(mma_gemm<0,0,0>, cudaFuncAttributeMaxDynamicSharedMemorySize, DS1);

    // operand preparation
    split_kernel<<<(NTOK * CDIM / 4 + 255) / 256, 256>>>(x, xh, xl, NTOK * CDIM / 4);
    transpose_kernel<0><<<dim3(HDIM/32, CDIM/32, 1), dim3(32, 8)>>>(rw1, rw1th, rw1tl, CDIM, HDIM);
    transpose_kernel<0><<<dim3(HDIM/32, HDIM/32, 1), dim3(32, 8)>>>(rw2, rw2th, rw2tl, HDIM, HDIM);
    transpose_kernel<1><<<dim3(HDIM/32, CDIM/32, EXPN), dim3(32, 8)>>>(ew1, ew1t, nullptr, CDIM, HDIM);
    transpose_kernel<1><<<dim3(CDIM/32, HDIM/32, EXPN), dim3(32, 8)>>>(ew2, ew2t, nullptr, HDIM, CDIM);

    // router MLP (3xTF32, fp32-exact class); GEMM1 writes h1 pre-split
    mma_gemm<1,1,1><<<dim3(HDIM/128, NTOK/128, 1), 256, DS3>>>(
        xh, xl, rw1th, rw1tl, rb1, h1h, h1l, CDIM, HDIM, 0, 0, 0, 0);
    mma_gemm<1,1,0><<<dim3(HDIM/128, NTOK/128, 1), 256, DS3>>>(
        h1h, h1l, rw2th, rw2tl, rb2, h2, nullptr, HDIM, HDIM, 0, 0, 0, 0);
    router_topk_kernel<<<NTOK, 256>>>(h2, rw3, rb3, eid, prob);
    positions_kernel<<<1, 1024>>>(eid, pos);

    // dispatch (pre-rna'd for expert GEMM1)
    {
        int n4 = (int)((size_t)EXPN * CAPN * CDIM / 4);
        zero_kernel<<<(n4 + 255) / 256, 256>>>((float4*)disp, n4);
    }
    dispatch_kernel<<<NFLAT, 256>>>(x, eid, pos, disp);

    // expert FFNs (1xTF32), batched over experts; GEMM1 writes eh pre-rna'd
    mma_gemm<0,1,2><<<dim3(HDIM/128, CAPN/128, EXPN), 256, DS1>>>(
        disp, nullptr, ew1t, nullptr, eb1, eh, nullptr, CDIM, HDIM,
        (long long)CAPN * CDIM, (long long)HDIM * CDIM, HDIM, (long long)CAPN * HDIM);
    mma_gemm<0,0,0><<<dim3(CDIM/128, CAPN/128, EXPN), 256, DS1>>>(
        eh, nullptr, ew2t, nullptr, eb2, eo, nullptr, HDIM, CDIM,
        (long long)CAPN * HDIM, (long long)CDIM * HDIM, CDIM, (long long)CAPN * CDIM);

    // combine
    combine_kernel<<<NTOK, 256>>>(eo, eid, prob, pos, out);
}